// round 17
// baseline (speedup 1.0000x reference)
#include <cuda_runtime.h>
#include <math.h>

#define SEQ   1024
#define VOCAB 8000
#define EMB   512
#define HID   1024
#define G3    (3*HID)        // 3072
#define NCTA  128            // persistent CTAs (one wave, <=148 SMs)
#define TPB   256            // 8 warps -> one hidden unit j per warp

// ---------------- device scratch (no allocations allowed) ----------------
__device__ float    g_gi_enc[SEQ*G3];   // precomputed x@Wih^T + bih (encoder)
__device__ float    g_gi_dec[SEQ*G3];   // precomputed (decoder, teacher forcing)
__device__ float    g_h[2][HID];        // double-buffered hidden state
__device__ int      g_dec_idx[SEQ];     // decoder input token ids
__device__ int      g_nsteps;           // first_eos+1 (or SEQ)
__device__ __align__(16) unsigned g_flag[NCTA];  // per-CTA barrier flags (packed)
__device__ unsigned g_base = 0;         // per-launch barrier epoch base

// ---------------- grid barrier: per-CTA flags, no atomics -----------------
// Arrive: CTA writes `target` (monotonic) into its own flag slot (release).
// Wait:  warp 0 polls all 128 flags with 32x v4 relaxed loads, wrap-safe
//        signed compare, then fence.acq_rel.gpu. No single-address atomic
//        serialization (the old bottleneck: ~3500 cyc/barrier).
__device__ __forceinline__ void gbar(unsigned target){
    __syncthreads();
    if (threadIdx.x < 32){
        if (threadIdx.x == 0)
            asm volatile("st.release.gpu.u32 [%0], %1;"
                         :: "l"(&g_flag[blockIdx.x]), "r"(target) : "memory");
        const uint4* f = ((const uint4*)g_flag) + threadIdx.x;
        for (;;){
            uint4 v;
            asm volatile("ld.relaxed.gpu.v4.u32 {%0,%1,%2,%3}, [%4];"
                         : "=r"(v.x), "=r"(v.y), "=r"(v.z), "=r"(v.w)
                         : "l"(f) : "memory");
            bool ok = ((int)(v.x - target) >= 0) & ((int)(v.y - target) >= 0) &
                      ((int)(v.z - target) >= 0) & ((int)(v.w - target) >= 0);
            if (__all_sync(0xffffffffu, ok)) break;
        }
        asm volatile("fence.acq_rel.gpu;" ::: "memory");
    }
    __syncthreads();
}

// ---------------- prep: decoder inputs + eos cutoff + barrier epoch ------
__global__ void prep_kernel(const int* __restrict__ target,
                            const int* __restrict__ sos_p,
                            const int* __restrict__ eos_p){
    int t = threadIdx.x;                     // 1024 threads
    __shared__ int mn;
    if (t == 0) mn = SEQ;
    __syncthreads();
    int eos = *eos_p;
    g_dec_idx[t] = (t == 0) ? *sos_p : target[t-1];
    if (target[t] == eos) atomicMin(&mn, t);
    __syncthreads();
    if (t == 0){
        g_nsteps = (mn + 1 < SEQ) ? (mn + 1) : SEQ;
        g_base  += 4096;                     // > max barriers per launch (2049)
    }
}

// ---------------- SGEMM: C[M,N] = gather(A)[M,K] * B[N,K]^T + bias -------
// BM=128, BN=64, BK=16, 256 threads, 8x4 micro-tile. All dims divide tiles.
__global__ void __launch_bounds__(256) sgemm_atbt(
    const float* __restrict__ Abase,  // [*,K] table (gather) or [M,K]
    const int*   __restrict__ rows,   // row index per m, or nullptr
    const float* __restrict__ B,      // [N,K]
    const float* __restrict__ bias,   // [N]
    float* __restrict__ C,            // [M,N]
    int M, int N, int K, int use_nvalid)
{
    const int BK = 16;
    __shared__ float As[16][128];
    __shared__ float Bs[16][64];
    int tid = threadIdx.x;
    int m0 = blockIdx.y * 128, n0 = blockIdx.x * 64;
    int tx = tid & 15, ty = tid >> 4;

    int aIdx0 = tid, aIdx1 = tid + 256;
    int am0 = aIdx0 >> 2, ak0 = (aIdx0 & 3) * 4;
    int am1 = aIdx1 >> 2, ak1 = (aIdx1 & 3) * 4;
    long arow0 = rows ? (long)rows[m0 + am0] : (long)(m0 + am0);
    long arow1 = rows ? (long)rows[m0 + am1] : (long)(m0 + am1);
    const float* Ap0 = Abase + arow0 * K;
    const float* Ap1 = Abase + arow1 * K;
    int bn_ = tid >> 2, bk_ = (tid & 3) * 4;
    const float* Bp = B + (long)(n0 + bn_) * K;

    float acc[8][4];
    #pragma unroll
    for (int i = 0; i < 8; ++i)
        #pragma unroll
        for (int j = 0; j < 4; ++j) acc[i][j] = 0.f;

    for (int kt = 0; kt < K; kt += BK){
        float4 va0 = *(const float4*)(Ap0 + kt + ak0);
        float4 va1 = *(const float4*)(Ap1 + kt + ak1);
        float4 vb  = *(const float4*)(Bp  + kt + bk_);
        As[ak0+0][am0]=va0.x; As[ak0+1][am0]=va0.y; As[ak0+2][am0]=va0.z; As[ak0+3][am0]=va0.w;
        As[ak1+0][am1]=va1.x; As[ak1+1][am1]=va1.y; As[ak1+2][am1]=va1.z; As[ak1+3][am1]=va1.w;
        Bs[bk_+0][bn_]=vb.x;  Bs[bk_+1][bn_]=vb.y;  Bs[bk_+2][bn_]=vb.z;  Bs[bk_+3][bn_]=vb.w;
        __syncthreads();
        #pragma unroll
        for (int k = 0; k < BK; ++k){
            float4 a0 = *(const float4*)&As[k][ty*8];
            float4 a1 = *(const float4*)&As[k][ty*8+4];
            float4 b0 = *(const float4*)&Bs[k][tx*4];
            float a_[8] = {a0.x,a0.y,a0.z,a0.w,a1.x,a1.y,a1.z,a1.w};
            float b_[4] = {b0.x,b0.y,b0.z,b0.w};
            #pragma unroll
            for (int i = 0; i < 8; ++i)
                #pragma unroll
                for (int j = 0; j < 4; ++j)
                    acc[i][j] = fmaf(a_[i], b_[j], acc[i][j]);
        }
        __syncthreads();
    }
    int nvalid = use_nvalid ? g_nsteps : M;
    #pragma unroll
    for (int i = 0; i < 8; ++i){
        int m = m0 + ty*8 + i;
        int n = n0 + tx*4;
        float4 o;
        if (m < nvalid){
            o.x = acc[i][0] + bias[n+0];
            o.y = acc[i][1] + bias[n+1];
            o.z = acc[i][2] + bias[n+2];
            o.w = acc[i][3] + bias[n+3];
        } else {
            o = make_float4(0.f, 0.f, 0.f, 0.f);
        }
        *(float4*)(C + (long)m * N + n) = o;
    }
}

// ---------------- recurrent persistent kernel ----------------------------
// Warp w of CTA b owns hidden unit j = 8b+w. Each lane holds 3x8 float4 of
// recurrent weights in REGISTERS (96 regs) -> no per-step weight traffic.
__device__ __forceinline__ void load_wregs(float4 wr[8], float4 wz[8], float4 wn[8],
                                           const float* __restrict__ W,
                                           int j, int lane){
    const float4* Wr = (const float4*)(W + (size_t)( 0*HID + j) * HID);
    const float4* Wz = (const float4*)(W + (size_t)( 1*HID + j) * HID);
    const float4* Wn = (const float4*)(W + (size_t)( 2*HID + j) * HID);
    #pragma unroll
    for (int q = 0; q < 8; ++q){
        wr[q] = Wr[lane + 32*q];
        wz[q] = Wz[lane + 32*q];
        wn[q] = Wn[lane + 32*q];
    }
}

__global__ void __launch_bounds__(TPB, 1) gru_persist(
    const int*   __restrict__ char_seq,
    const float* __restrict__ enc_state,
    const float* __restrict__ enc_whh, const float* __restrict__ enc_bhh,
    const float* __restrict__ dec_whh, const float* __restrict__ dec_bhh,
    float* __restrict__ states)       // [SEQ, HID] region of d_out
{
    __shared__ float sh[HID];
    int tid  = threadIdx.x;
    int w    = tid >> 5, lane = tid & 31;
    int j    = blockIdx.x * 8 + w;    // global hidden index this warp owns

    float4 wr[8], wz[8], wn[8];
    load_wregs(wr, wz, wn, enc_whh, j, lane);
    float br = enc_bhh[j], bz = enc_bhh[HID + j], bn = enc_bhh[2*HID + j];

    unsigned bstep = *(volatile unsigned*)&g_base;

    if (tid < 8) g_h[0][blockIdx.x*8 + tid] = enc_state[blockIdx.x*8 + tid];
    gbar(++bstep);

    int p = 0;

    // ------------------ encoder: 1024 masked GRU steps ------------------
    for (int t = 0; t < SEQ; ++t){
        ((float4*)sh)[tid] = __ldcg(((const float4*)g_h[p]) + tid);  // L2, cross-SM
        __syncthreads();

        const float* gi = g_gi_enc + (size_t)t * G3;
        float gir = __ldg(gi + j), giz = __ldg(gi + HID + j), gin = __ldg(gi + 2*HID + j);
        int ct = __ldg(char_seq + t);

        float ar = 0.f, az = 0.f, an = 0.f;
        #pragma unroll
        for (int q = 0; q < 8; ++q){
            float4 hh = ((const float4*)sh)[lane + 32*q];
            ar = fmaf(wr[q].x,hh.x, fmaf(wr[q].y,hh.y, fmaf(wr[q].z,hh.z, fmaf(wr[q].w,hh.w, ar))));
            az = fmaf(wz[q].x,hh.x, fmaf(wz[q].y,hh.y, fmaf(wz[q].z,hh.z, fmaf(wz[q].w,hh.w, az))));
            an = fmaf(wn[q].x,hh.x, fmaf(wn[q].y,hh.y, fmaf(wn[q].z,hh.z, fmaf(wn[q].w,hh.w, an))));
        }
        #pragma unroll
        for (int o = 16; o; o >>= 1){
            ar += __shfl_down_sync(0xffffffffu, ar, o);
            az += __shfl_down_sync(0xffffffffu, az, o);
            an += __shfl_down_sync(0xffffffffu, an, o);
        }

        if (lane == 0){
            float r  = 1.f / (1.f + __expf(-(gir + ar + br)));
            float z  = 1.f / (1.f + __expf(-(giz + az + bz)));
            float n  = tanhf(gin + r * (an + bn));
            float hp = sh[j];
            float hn = (1.f - z) * n + z * hp;
            if (ct == 0) hn = hp;                 // mask: keep state on pad tokens
            g_h[p ^ 1][j] = hn;
        }
        gbar(++bstep);
        p ^= 1;
    }

    // ------------------ decoder: n_steps GRU steps -----------------------
    load_wregs(wr, wz, wn, dec_whh, j, lane);
    br = dec_bhh[j]; bz = dec_bhh[HID + j]; bn = dec_bhh[2*HID + j];
    int nsteps = g_nsteps;

    for (int t = 0; t < nsteps; ++t){
        ((float4*)sh)[tid] = __ldcg(((const float4*)g_h[p]) + tid);
        __syncthreads();

        const float* gi = g_gi_dec + (size_t)t * G3;
        float gir = __ldg(gi + j), giz = __ldg(gi + HID + j), gin = __ldg(gi + 2*HID + j);

        float ar = 0.f, az = 0.f, an = 0.f;
        #pragma unroll
        for (int q = 0; q < 8; ++q){
            float4 hh = ((const float4*)sh)[lane + 32*q];
            ar = fmaf(wr[q].x,hh.x, fmaf(wr[q].y,hh.y, fmaf(wr[q].z,hh.z, fmaf(wr[q].w,hh.w, ar))));
            az = fmaf(wz[q].x,hh.x, fmaf(wz[q].y,hh.y, fmaf(wz[q].z,hh.z, fmaf(wz[q].w,hh.w, az))));
            an = fmaf(wn[q].x,hh.x, fmaf(wn[q].y,hh.y, fmaf(wn[q].z,hh.z, fmaf(wn[q].w,hh.w, an))));
        }
        #pragma unroll
        for (int o = 16; o; o >>= 1){
            ar += __shfl_down_sync(0xffffffffu, ar, o);
            az += __shfl_down_sync(0xffffffffu, az, o);
            an += __shfl_down_sync(0xffffffffu, an, o);
        }

        if (lane == 0){
            float r  = 1.f / (1.f + __expf(-(gir + ar + br)));
            float z  = 1.f / (1.f + __expf(-(giz + az + bz)));
            float n  = tanhf(gin + r * (an + bn));
            float hp = sh[j];
            float hn = (1.f - z) * n + z * hp;
            g_h[p ^ 1][j] = hn;
            states[(size_t)t * HID + j] = hn;     // valid[t]==1 for t<nsteps
        }
        gbar(++bstep);
        p ^= 1;
    }

    // zero-pad states beyond eos cutoff
    for (int t = nsteps; t < SEQ; ++t)
        if (tid < 8) states[(size_t)t * HID + blockIdx.x*8 + tid] = 0.f;
}

// ---------------- launch ---------------------------------------------------
extern "C" void kernel_launch(void* const* d_in, const int* in_sizes, int n_in,
                              void* d_out, int out_size)
{
    const int*   char_seq  = (const int*)  d_in[0];
    const int*   target    = (const int*)  d_in[1];
    const float* enc_state = (const float*)d_in[2];
    const float* emb       = (const float*)d_in[3];
    const float* enc_wih   = (const float*)d_in[4];
    const float* enc_whh   = (const float*)d_in[5];
    const float* enc_bih   = (const float*)d_in[6];
    const float* enc_bhh   = (const float*)d_in[7];
    const float* dec_wih   = (const float*)d_in[8];
    const float* dec_whh   = (const float*)d_in[9];
    const float* dec_bih   = (const float*)d_in[10];
    const float* dec_bhh   = (const float*)d_in[11];
    const float* out_w     = (const float*)d_in[12];
    const float* out_b     = (const float*)d_in[13];
    const int*   sos_p     = (const int*)  d_in[14];
    const int*   eos_p     = (const int*)  d_in[15];

    float* out    = (float*)d_out;
    float* scores = out;                          // [SEQ, VOCAB]
    float* states = out + (size_t)SEQ * VOCAB;    // [SEQ, HID]

    void *p_gi_enc = nullptr, *p_gi_dec = nullptr, *p_dec_idx = nullptr;
    cudaGetSymbolAddress(&p_gi_enc, g_gi_enc);
    cudaGetSymbolAddress(&p_gi_dec, g_gi_dec);
    cudaGetSymbolAddress(&p_dec_idx, g_dec_idx);

    // 1) decoder input ids + eos cutoff + barrier epoch bump
    prep_kernel<<<1, SEQ>>>(target, sos_p, eos_p);

    // 2) input-side gates for all steps (parallel GEMMs)
    sgemm_atbt<<<dim3(G3/64, SEQ/128), 256>>>(
        emb, char_seq, enc_wih, enc_bih, (float*)p_gi_enc, SEQ, G3, EMB, 0);
    sgemm_atbt<<<dim3(G3/64, SEQ/128), 256>>>(
        emb, (const int*)p_dec_idx, dec_wih, dec_bih, (float*)p_gi_dec, SEQ, G3, EMB, 0);

    // 3) sequential recurrence: persistent kernel, weights register-resident
    gru_persist<<<NCTA, TPB>>>(char_seq, enc_state,
                               enc_whh, enc_bhh, dec_whh, dec_bhh, states);

    // 4) output projection (rows >= n_steps zeroed per valid mask)
    sgemm_atbt<<<dim3(VOCAB/64, SEQ/128), 256>>>(
        states, nullptr, out_w, out_b, scores, SEQ, VOCAB, HID, 1);
}